// round 11
// baseline (speedup 1.0000x reference)
#include <cuda_runtime.h>
#include <cuda_fp16.h>

#define N_TASK 50000
#define N_RET  20000
#define N_DRAM 5000
#define N_LINKN 100000
#define E_RET  1000000
#define E_DRAM 250000
#define E_LINK 2000000
#define HD 64
#define SCAN_NBLK 98   /* ceil(100000/1024) */
#define RD_BLOCKS ((E_RET + E_DRAM + 255) / 256)   /* 4883 */

// ---------------- device scratch ----------------
__device__ float    g_s_ret[N_RET];
__device__ float    g_s_dram[N_DRAM];
__device__ float2   g_sc_link[N_LINKN];   // (sum, count) -> after scan: (sum, offs-bits)
__device__ uint2    g_mm[3 * N_TASK];     // (max_enc, min_enc) per (etype, task)
__device__ __half   g_h_task[N_TASK * HD];
__device__ int      g_cnt[N_LINKN];
__device__ int      g_offs[N_LINKN];
__device__ int      g_rank[E_LINK];       // edge's rank within its module
__device__ int      g_csr[E_LINK];
__device__ int      g_part[128];
__device__ int      g_done;               // scan phase-1 join
__device__ int      g_done2;              // scan completion (consumed by link branch)

// order-preserving float<->uint encoding (all real floats encode > 0)
__device__ __forceinline__ unsigned encf(float f) {
    unsigned u = __float_as_uint(f);
    return (u & 0x80000000u) ? ~u : (u | 0x80000000u);
}
__device__ __forceinline__ float decf(unsigned u) {
    return __uint_as_float((u & 0x80000000u) ? (u & 0x7FFFFFFFu) : ~u);
}

__device__ __forceinline__ float tanh_fast(float x) {
    float y;
    asm("tanh.approx.f32 %0, %1;" : "=f"(y) : "f"(x));
    return y;
}

// ---------------- init ----------------
__global__ void k_init() {
    int i = blockIdx.x * blockDim.x + threadIdx.x;
    if (i == 0) { g_done = 0; g_done2 = 0; }
    if (i < N_RET)  g_s_ret[i]  = 0.f;
    if (i < N_DRAM) g_s_dram[i] = 0.f;
    if (i < N_LINKN) g_sc_link[i] = make_float2(0.f, 0.f);
}

// ---------------- fused segment sums + g_mm init: 1 edge / thread ---------
#define NE_ALL (E_LINK + E_RET + E_DRAM)
__global__ void k_sum(const float* __restrict__ fl, const int* __restrict__ ml,
                      const float* __restrict__ fr, const int* __restrict__ mr,
                      const float* __restrict__ fd, const int* __restrict__ md) {
    int i = blockIdx.x * blockDim.x + threadIdx.x;
    if (i < E_LINK) {
        int m = __ldg(&ml[i]);
        float2 old = atomicAdd(&g_sc_link[m], make_float2(__ldg(&fl[i]), 1.0f));
        g_rank[i] = (int)old.y;           // this edge's rank within module m
    } else if (i < E_LINK + E_RET) {
        int j = i - E_LINK;
        atomicAdd(&g_s_ret[__ldg(&mr[j])], __ldg(&fr[j]));
    } else if (i < NE_ALL) {
        int j = i - E_LINK - E_RET;
        atomicAdd(&g_s_dram[__ldg(&md[j])], __ldg(&fd[j]));
    } else if (i < NE_ALL + 3 * N_TASK) {
        g_mm[i - NE_ALL] = make_uint2(0u, 0xFFFFFFFFu);   // init for minmax
    }
}

// ---------------- merged: scan (bids 0..97) + ret/dram minmax + link minmax
// scan bids are first in wave 1; link blocks (bid >= 98+4883) enter waves >= 5,
// so their poll of g_done2 is effectively a pass-through check.
__global__ void k_mmscan(const int* __restrict__ ml, const int* __restrict__ tl,
                         const int* __restrict__ mr, const int* __restrict__ tr,
                         const int* __restrict__ md, const int* __restrict__ td) {
    if (blockIdx.x < SCAN_NBLK) {
        // ---- coalesced scan of link counts; writes offs/cnt + packs offs into sc.y
        __shared__ int sh[256];
        int b = blockIdx.x, tid = threadIdx.x;
        int i = b * 1024 + tid * 4;

        int c0 = 0, c1 = 0, c2 = 0, c3 = 0, s = 0;
        if (i < N_LINKN) {
            float4 a = *(const float4*)&g_sc_link[i];
            float4 d = *(const float4*)&g_sc_link[i + 2];
            c0 = (int)a.y; c1 = (int)a.w; c2 = (int)d.y; c3 = (int)d.w;
            s = c0 + c1 + c2 + c3;
        }

        sh[tid] = s;
        __syncthreads();
        for (int off = 1; off < 256; off <<= 1) {
            int u = (tid >= off) ? sh[tid - off] : 0;
            __syncthreads();
            sh[tid] += u;
            __syncthreads();
        }
        int incl = sh[tid];
        int blk_total = sh[255];

        if (tid == 0) {
            g_part[b] = blk_total;
            __threadfence();
            atomicAdd(&g_done, 1);
            while (*(volatile int*)&g_done < SCAN_NBLK) { }
        }
        __syncthreads();

        sh[tid] = (tid < b) ? ((volatile int*)g_part)[tid] : 0;
        __syncthreads();
        for (int off = 128; off > 0; off >>= 1) {
            if (tid < off) sh[tid] += sh[tid + off];
            __syncthreads();
        }
        int base = sh[0];

        int run = base + incl - s;
        if (i < N_LINKN) {
            int4 o;
            o.x = run;
            o.y = run + c0;
            o.z = o.y + c1;
            o.w = o.z + c2;
            *(int4*)&g_offs[i] = o;
            *(int4*)&g_cnt[i]  = make_int4(c0, c1, c2, c3);
            int2* scl = (int2*)g_sc_link;
            scl[i + 0].y = o.x;
            scl[i + 1].y = o.y;
            scl[i + 2].y = o.z;
            scl[i + 3].y = o.w;
        }
        // publish completion: all stores fenced, then count up
        __threadfence();
        __syncthreads();
        if (tid == 0) atomicAdd(&g_done2, 1);
    } else if (blockIdx.x < SCAN_NBLK + RD_BLOCKS) {
        // ---- ret/dram min/max: independent of the scan, runs immediately
        int i = (blockIdx.x - SCAN_NBLK) * blockDim.x + threadIdx.x;
        if (i < E_RET) {
            unsigned k = encf(g_s_ret[__ldg(&mr[i])]);
            int t = __ldg(&tr[i]);
            atomicMax(&g_mm[0 * N_TASK + t].x, k);
            atomicMin(&g_mm[0 * N_TASK + t].y, k);
        } else if (i < E_RET + E_DRAM) {
            int j = i - E_RET;
            unsigned k = encf(g_s_dram[__ldg(&md[j])]);
            int t = __ldg(&td[j]);
            atomicMax(&g_mm[1 * N_TASK + t].x, k);
            atomicMin(&g_mm[1 * N_TASK + t].y, k);
        }
    } else {
        // ---- link min/max + CSR scatter; needs scan output (sc.y offs bits)
        int i = (blockIdx.x - SCAN_NBLK - RD_BLOCKS) * blockDim.x + threadIdx.x;
        int m = 0, t = 0, r = 0;
        bool ok = (i < E_LINK);
        if (ok) {                               // prefetch coalesced operands
            m = __ldg(&ml[i]);
            t = __ldg(&tl[i]);
            r = __ldg(&g_rank[i]);
        }
        if (threadIdx.x == 0) {
            while (*(volatile int*)&g_done2 < SCAN_NBLK) __nanosleep(128);
        }
        __syncthreads();
        __threadfence();                        // acquire: order loads after flag
        if (ok) {
            float2 sc = *(const float2*)&g_sc_link[m];   // one 8B scattered load
            unsigned k = encf(sc.x);
            atomicMax(&g_mm[2 * N_TASK + t].x, k);
            atomicMin(&g_mm[2 * N_TASK + t].y, k);
            g_csr[__float_as_int(sc.y) + r] = t;
        }
    }
}

// ---------------- task update: tanh(v @ Wtask^T + b), f32x2 FFMA ----------
// Thread (lane tx, warp ty): columns h = tx and tx+32, tasks t0 = ty*8.
__global__ void k_task(const float* __restrict__ Wret,  const float* __restrict__ bret,
                       const float* __restrict__ Wdram, const float* __restrict__ bdram,
                       const float* __restrict__ Wlink, const float* __restrict__ blink,
                       const float* __restrict__ Wtask, const float* __restrict__ btask) {
    extern __shared__ float sh[];
    float*  sV  = sh;                                   // 12288 floats
    float2* sW2 = (float2*)(sh + 64 * 192);             // 64*97 float2
    uint2*  sMM = (uint2*)(sh + 64 * 192 + 64 * 97 * 2);// 192 uint2
    float*  sWe = (float*)(sMM + 192);                  // 192 floats
    float*  sBe = sWe + 192;                            // 192 floats

    int tb = blockIdx.x * 64;
    int tid = threadIdx.x;

    if (tid < 192) {
        int et = tid >> 6, hh = tid & 63;
        const float* We = (et == 0) ? Wret : (et == 1) ? Wdram : Wlink;
        const float* be = (et == 0) ? bret : (et == 1) ? bdram : blink;
        sWe[tid] = We[hh];
        sBe[tid] = be[hh];
    }
    for (int idx = tid; idx < 64 * 3; idx += 256) {
        int tl = idx / 3, et = idx - tl * 3;
        int t = tb + tl;
        sMM[tl * 3 + et] = (t < N_TASK) ? g_mm[et * N_TASK + t]
                                        : make_uint2(0u, 0xFFFFFFFFu);
    }
    for (int idx = tid; idx < 64 * 96; idx += 256) {
        int h = idx / 96, kp = idx - h * 96;
        sW2[h * 97 + kp] = *(const float2*)&Wtask[h * 192 + 2 * kp];
    }
    __syncthreads();

    for (int idx = tid; idx < 64 * 192; idx += 256) {
        int tl = idx / 192, k = idx - tl * 192;
        int et = k >> 6, h = k & 63;
        float v = 0.f;
        uint2 mm = sMM[tl * 3 + et];
        if (mm.x != 0u) {
            float w = sWe[et * 64 + h];
            float sv = (w >= 0.f) ? decf(mm.x) : decf(mm.y);
            v = tanh_fast(fmaf(w, sv, sBe[et * 64 + h]));
        }
        sV[idx] = v;
    }
    __syncthreads();

    int tx = tid & 31, ty = tid >> 5;
    int t0 = ty * 8;

    unsigned long long acc0[8], acc1[8];
#pragma unroll
    for (int i = 0; i < 8; i++) { acc0[i] = 0ull; acc1[i] = 0ull; }

    const float2* w0row = sW2 + tx * 97;
    const float2* w1row = sW2 + (tx + 32) * 97;
    const float*  vb    = sV + t0 * 192;

#pragma unroll 4
    for (int kp = 0; kp < 96; kp += 2) {
        unsigned long long wa0 = *(const unsigned long long*)&w0row[kp];
        unsigned long long wa1 = *(const unsigned long long*)&w0row[kp + 1];
        unsigned long long wb0 = *(const unsigned long long*)&w1row[kp];
        unsigned long long wb1 = *(const unsigned long long*)&w1row[kp + 1];
#pragma unroll
        for (int i = 0; i < 8; i++) {
            ulonglong2 v = *(const ulonglong2*)(vb + i * 192 + 2 * kp);
            asm("fma.rn.f32x2 %0, %1, %2, %0;" : "+l"(acc0[i]) : "l"(v.x), "l"(wa0));
            asm("fma.rn.f32x2 %0, %1, %2, %0;" : "+l"(acc0[i]) : "l"(v.y), "l"(wa1));
            asm("fma.rn.f32x2 %0, %1, %2, %0;" : "+l"(acc1[i]) : "l"(v.x), "l"(wb0));
            asm("fma.rn.f32x2 %0, %1, %2, %0;" : "+l"(acc1[i]) : "l"(v.y), "l"(wb1));
        }
    }

    float bh0 = btask[tx], bh1 = btask[tx + 32];
#pragma unroll
    for (int i = 0; i < 8; i++) {
        int t = tb + t0 + i;
        if (t < N_TASK) {
            float lo, hi;
            asm("mov.b64 {%0, %1}, %2;" : "=f"(lo), "=f"(hi) : "l"(acc0[i]));
            g_h_task[t * 64 + tx] = __float2half(tanh_fast(lo + hi + bh0));
            asm("mov.b64 {%0, %1}, %2;" : "=f"(lo), "=f"(hi) : "l"(acc1[i]));
            g_h_task[t * 64 + tx + 32] = __float2half(tanh_fast(lo + hi + bh1));
        }
    }
}

// ---------------- link mean: warp per link node, CSR gather (fp16 h) ------
__global__ void k_linkmean(float* __restrict__ out) {
    int gw = (blockIdx.x * blockDim.x + threadIdx.x) >> 5;
    if (gw >= N_LINKN) return;
    int lane = threadIdx.x & 31;
    int beg = g_offs[gw];
    int n = g_cnt[gw];
    float ax = 0.f, ay = 0.f;
    int j = 0;
    for (; j + 3 < n; j += 4) {
        int t0 = __ldg(&g_csr[beg + j + 0]);
        int t1 = __ldg(&g_csr[beg + j + 1]);
        int t2 = __ldg(&g_csr[beg + j + 2]);
        int t3 = __ldg(&g_csr[beg + j + 3]);
        float2 v0 = __half22float2(*(const __half2*)&g_h_task[t0 * 64 + lane * 2]);
        float2 v1 = __half22float2(*(const __half2*)&g_h_task[t1 * 64 + lane * 2]);
        float2 v2 = __half22float2(*(const __half2*)&g_h_task[t2 * 64 + lane * 2]);
        float2 v3 = __half22float2(*(const __half2*)&g_h_task[t3 * 64 + lane * 2]);
        ax += (v0.x + v1.x) + (v2.x + v3.x);
        ay += (v0.y + v1.y) + (v2.y + v3.y);
    }
    for (; j < n; j++) {
        int t = __ldg(&g_csr[beg + j]);
        float2 v = __half22float2(*(const __half2*)&g_h_task[t * 64 + lane * 2]);
        ax += v.x;
        ay += v.y;
    }
    float inv = (n > 0) ? 1.0f / (float)n : 0.f;
    float2 o;
    o.x = ax * inv;
    o.y = ay * inv;
    *(float2*)&out[(size_t)gw * 64 + lane * 2] = o;
}

// ---------------- launch ----------------
extern "C" void kernel_launch(void* const* d_in, const int* in_sizes, int n_in,
                              void* d_out, int out_size) {
    const float* feat_ret  = (const float*)d_in[0];
    const float* feat_dram = (const float*)d_in[1];
    const float* feat_link = (const float*)d_in[2];
    const float* W_ret   = (const float*)d_in[3];
    const float* b_ret   = (const float*)d_in[4];
    const float* W_dram  = (const float*)d_in[5];
    const float* b_dram  = (const float*)d_in[6];
    const float* W_link  = (const float*)d_in[7];
    const float* b_link  = (const float*)d_in[8];
    const float* W_task  = (const float*)d_in[9];
    const float* b_task  = (const float*)d_in[10];
    const int* task_ret  = (const int*)d_in[11];
    const int* mod_ret   = (const int*)d_in[12];
    const int* task_dram = (const int*)d_in[13];
    const int* mod_dram  = (const int*)d_in[14];
    const int* task_link = (const int*)d_in[15];
    const int* mod_link  = (const int*)d_in[16];
    float* out = (float*)d_out;

    const int TPB = 256;
    const int smem_task = 64 * 192 * 4 + 64 * 97 * 8 + 192 * 8 + 192 * 4 + 192 * 4;
    cudaFuncSetAttribute(k_task, cudaFuncAttributeMaxDynamicSharedMemorySize, smem_task);

    k_init<<<(N_LINKN + TPB - 1) / TPB, TPB>>>();

    // segment sums + g_mm init in tail range
    k_sum<<<(NE_ALL + 3 * N_TASK + TPB - 1) / TPB, TPB>>>(feat_link, mod_link,
                                                          feat_ret,  mod_ret,
                                                          feat_dram, mod_dram);

    // merged: scan (bids 0..97) + ret/dram minmax + link minmax/CSR (spin on scan)
    k_mmscan<<<SCAN_NBLK + RD_BLOCKS + (E_LINK + TPB - 1) / TPB, TPB>>>(
        mod_link, task_link, mod_ret, task_ret, mod_dram, task_dram);

    k_task<<<(N_TASK + 63) / 64, TPB, smem_task>>>(W_ret, b_ret, W_dram, b_dram,
                                                   W_link, b_link, W_task, b_task);

    k_linkmean<<<(N_LINKN * 32 + TPB - 1) / TPB, TPB>>>(out);
}

// round 12
// speedup vs baseline: 1.0296x; 1.0296x over previous
#include <cuda_runtime.h>
#include <cuda_fp16.h>

#define N_TASK 50000
#define N_RET  20000
#define N_DRAM 5000
#define N_LINKN 100000
#define E_RET  1000000
#define E_DRAM 250000
#define E_LINK 2000000
#define HD 64
#define SCAN_NBLK 98   /* ceil(100000/1024) */

// ---------------- device scratch ----------------
__device__ float    g_s_ret[N_RET];
__device__ float    g_s_dram[N_DRAM];
__device__ float2   g_sc_link[N_LINKN];   // (sum, count) -> after scan: (sum, offs-bits)
__device__ uint2    g_mm[3 * N_TASK];     // (max_enc, min_enc) per (etype, task)
__device__ __half   g_h_task[N_TASK * HD];
__device__ int      g_cnt[N_LINKN];
__device__ int      g_offs[N_LINKN];
__device__ int      g_rank[E_LINK];       // edge's rank within its module
__device__ int      g_csr[E_LINK];
__device__ int      g_part[128];
__device__ int      g_done;

// order-preserving float<->uint encoding (all real floats encode > 0)
__device__ __forceinline__ unsigned encf(float f) {
    unsigned u = __float_as_uint(f);
    return (u & 0x80000000u) ? ~u : (u | 0x80000000u);
}
__device__ __forceinline__ float decf(unsigned u) {
    return __uint_as_float((u & 0x80000000u) ? (u & 0x7FFFFFFFu) : ~u);
}

__device__ __forceinline__ float tanh_fast(float x) {
    float y;
    asm("tanh.approx.f32 %0, %1;" : "=f"(y) : "f"(x));
    return y;
}

// ---------------- init ----------------
__global__ void k_init() {
    int i = blockIdx.x * blockDim.x + threadIdx.x;
    if (i == 0) g_done = 0;
    if (i < N_RET)  g_s_ret[i]  = 0.f;
    if (i < N_DRAM) g_s_dram[i] = 0.f;
    if (i < N_LINKN) g_sc_link[i] = make_float2(0.f, 0.f);
    if (i < N_TASK) {
#pragma unroll
        for (int et = 0; et < 3; et++)
            g_mm[et * N_TASK + i] = make_uint2(0u, 0xFFFFFFFFu);
    }
}

// ---------------- fused segment sums: 1 edge / thread ----------------
__global__ void k_sum(const float* __restrict__ fl, const int* __restrict__ ml,
                      const float* __restrict__ fr, const int* __restrict__ mr,
                      const float* __restrict__ fd, const int* __restrict__ md) {
    int i = blockIdx.x * blockDim.x + threadIdx.x;
    if (i < E_LINK) {
        int m = __ldg(&ml[i]);
        float2 old = atomicAdd(&g_sc_link[m], make_float2(__ldg(&fl[i]), 1.0f));
        g_rank[i] = (int)old.y;           // this edge's rank within module m
    } else if (i < E_LINK + E_RET) {
        int j = i - E_LINK;
        atomicAdd(&g_s_ret[__ldg(&mr[j])], __ldg(&fr[j]));
    } else if (i < E_LINK + E_RET + E_DRAM) {
        int j = i - E_LINK - E_RET;
        atomicAdd(&g_s_dram[__ldg(&md[j])], __ldg(&fd[j]));
    }
}

// ---------------- single-kernel scan: publish partial, spin-join, resume ---
// grid = 98 blocks < 148 SMs -> all co-resident in wave 1 -> spin is safe.
__global__ void k_scan() {
    __shared__ int sh[256];
    int b = blockIdx.x, tid = threadIdx.x;
    int i = b * 1024 + tid * 4;

    int c0 = 0, c1 = 0, c2 = 0, c3 = 0, s = 0;
    if (i < N_LINKN) {
        float4 a = *(const float4*)&g_sc_link[i];
        float4 d = *(const float4*)&g_sc_link[i + 2];
        c0 = (int)a.y; c1 = (int)a.w; c2 = (int)d.y; c3 = (int)d.w;
        s = c0 + c1 + c2 + c3;
    }

    sh[tid] = s;
    __syncthreads();
    for (int off = 1; off < 256; off <<= 1) {
        int u = (tid >= off) ? sh[tid - off] : 0;
        __syncthreads();
        sh[tid] += u;
        __syncthreads();
    }
    int incl = sh[tid];
    int blk_total = sh[255];

    if (tid == 0) {
        g_part[b] = blk_total;
        __threadfence();
        atomicAdd(&g_done, 1);
        while (*(volatile int*)&g_done < SCAN_NBLK) { }
    }
    __syncthreads();

    sh[tid] = (tid < b) ? ((volatile int*)g_part)[tid] : 0;
    __syncthreads();
    for (int off = 128; off > 0; off >>= 1) {
        if (tid < off) sh[tid] += sh[tid + off];
        __syncthreads();
    }
    int base = sh[0];

    int run = base + incl - s;
    if (i < N_LINKN) {
        int4 o;
        o.x = run;
        o.y = run + c0;
        o.z = o.y + c1;
        o.w = o.z + c2;
        *(int4*)&g_offs[i] = o;
        *(int4*)&g_cnt[i]  = make_int4(c0, c1, c2, c3);
        int2* scl = (int2*)g_sc_link;
        scl[i + 0].y = o.x;
        scl[i + 1].y = o.y;
        scl[i + 2].y = o.z;
        scl[i + 3].y = o.w;
    }
}

// ---------------- fused per-task min/max (link branch also scatters CSR) --
__global__ void k_mm(const int* __restrict__ ml, const int* __restrict__ tl,
                     const int* __restrict__ mr, const int* __restrict__ tr,
                     const int* __restrict__ md, const int* __restrict__ td) {
    int i = blockIdx.x * blockDim.x + threadIdx.x;
    if (i < E_LINK) {
        int m = __ldg(&ml[i]);
        int t = __ldg(&tl[i]);
        float2 sc = *(const float2*)&g_sc_link[m];   // one 8B scattered load
        unsigned k = encf(sc.x);
        atomicMax(&g_mm[2 * N_TASK + t].x, k);
        atomicMin(&g_mm[2 * N_TASK + t].y, k);
        int p = __float_as_int(sc.y) + __ldg(&g_rank[i]);
        g_csr[p] = t;
    } else if (i < E_LINK + E_RET) {
        int j = i - E_LINK;
        unsigned k = encf(g_s_ret[__ldg(&mr[j])]);
        int t = __ldg(&tr[j]);
        atomicMax(&g_mm[0 * N_TASK + t].x, k);
        atomicMin(&g_mm[0 * N_TASK + t].y, k);
    } else if (i < E_LINK + E_RET + E_DRAM) {
        int j = i - E_LINK - E_RET;
        unsigned k = encf(g_s_dram[__ldg(&md[j])]);
        int t = __ldg(&td[j]);
        atomicMax(&g_mm[1 * N_TASK + t].x, k);
        atomicMin(&g_mm[1 * N_TASK + t].y, k);
    }
}

// ---------------- task update: tanh(v @ Wtask^T + b), f32x2 FFMA ----------
// 512 threads/block, tile = 64 tasks x 64 cols. Thread (lane tx, warp ty):
// columns tx and tx+32, tasks t0 = ty*4. 2 blocks/SM -> 32 warps resident.
__global__ void __launch_bounds__(512, 2)
k_task(const float* __restrict__ Wret,  const float* __restrict__ bret,
       const float* __restrict__ Wdram, const float* __restrict__ bdram,
       const float* __restrict__ Wlink, const float* __restrict__ blink,
       const float* __restrict__ Wtask, const float* __restrict__ btask) {
    extern __shared__ float sh[];
    float*  sV  = sh;                                   // 12288 floats
    float2* sW2 = (float2*)(sh + 64 * 192);             // 64*97 float2
    uint2*  sMM = (uint2*)(sh + 64 * 192 + 64 * 97 * 2);// 192 uint2
    float*  sWe = (float*)(sMM + 192);                  // 192 floats
    float*  sBe = sWe + 192;                            // 192 floats

    int tb = blockIdx.x * 64;
    int tid = threadIdx.x;

    if (tid < 192) {
        int et = tid >> 6, hh = tid & 63;
        const float* We = (et == 0) ? Wret : (et == 1) ? Wdram : Wlink;
        const float* be = (et == 0) ? bret : (et == 1) ? bdram : blink;
        sWe[tid] = We[hh];
        sBe[tid] = be[hh];
    }
    for (int idx = tid; idx < 64 * 3; idx += 512) {
        int tl = idx / 3, et = idx - tl * 3;
        int t = tb + tl;
        sMM[tl * 3 + et] = (t < N_TASK) ? g_mm[et * N_TASK + t]
                                        : make_uint2(0u, 0xFFFFFFFFu);
    }
    for (int idx = tid; idx < 64 * 96; idx += 512) {
        int h = idx / 96, kp = idx - h * 96;
        sW2[h * 97 + kp] = *(const float2*)&Wtask[h * 192 + 2 * kp];
    }
    __syncthreads();

    for (int idx = tid; idx < 64 * 192; idx += 512) {
        int tl = idx / 192, k = idx - tl * 192;
        int et = k >> 6, h = k & 63;
        float v = 0.f;
        uint2 mm = sMM[tl * 3 + et];
        if (mm.x != 0u) {
            float w = sWe[et * 64 + h];
            float sv = (w >= 0.f) ? decf(mm.x) : decf(mm.y);
            v = tanh_fast(fmaf(w, sv, sBe[et * 64 + h]));
        }
        sV[idx] = v;
    }
    __syncthreads();

    int tx = tid & 31, ty = tid >> 5;    // ty in 0..15
    int t0 = ty * 4;                     // 4 tasks per thread

    unsigned long long acc0[4], acc1[4];
#pragma unroll
    for (int i = 0; i < 4; i++) { acc0[i] = 0ull; acc1[i] = 0ull; }

    const float2* w0row = sW2 + tx * 97;
    const float2* w1row = sW2 + (tx + 32) * 97;
    const float*  vb    = sV + t0 * 192;

#pragma unroll 4
    for (int kp = 0; kp < 96; kp += 2) {
        unsigned long long wa0 = *(const unsigned long long*)&w0row[kp];
        unsigned long long wa1 = *(const unsigned long long*)&w0row[kp + 1];
        unsigned long long wb0 = *(const unsigned long long*)&w1row[kp];
        unsigned long long wb1 = *(const unsigned long long*)&w1row[kp + 1];
#pragma unroll
        for (int i = 0; i < 4; i++) {
            ulonglong2 v = *(const ulonglong2*)(vb + i * 192 + 2 * kp);
            asm("fma.rn.f32x2 %0, %1, %2, %0;" : "+l"(acc0[i]) : "l"(v.x), "l"(wa0));
            asm("fma.rn.f32x2 %0, %1, %2, %0;" : "+l"(acc0[i]) : "l"(v.y), "l"(wa1));
            asm("fma.rn.f32x2 %0, %1, %2, %0;" : "+l"(acc1[i]) : "l"(v.x), "l"(wb0));
            asm("fma.rn.f32x2 %0, %1, %2, %0;" : "+l"(acc1[i]) : "l"(v.y), "l"(wb1));
        }
    }

    float bh0 = btask[tx], bh1 = btask[tx + 32];
#pragma unroll
    for (int i = 0; i < 4; i++) {
        int t = tb + t0 + i;
        if (t < N_TASK) {
            float lo, hi;
            asm("mov.b64 {%0, %1}, %2;" : "=f"(lo), "=f"(hi) : "l"(acc0[i]));
            g_h_task[t * 64 + tx] = __float2half(tanh_fast(lo + hi + bh0));
            asm("mov.b64 {%0, %1}, %2;" : "=f"(lo), "=f"(hi) : "l"(acc1[i]));
            g_h_task[t * 64 + tx + 32] = __float2half(tanh_fast(lo + hi + bh1));
        }
    }
}

// ---------------- link mean: warp per link node, CSR gather (fp16 h) ------
__global__ void k_linkmean(float* __restrict__ out) {
    int gw = (blockIdx.x * blockDim.x + threadIdx.x) >> 5;
    if (gw >= N_LINKN) return;
    int lane = threadIdx.x & 31;
    int beg = g_offs[gw];
    int n = g_cnt[gw];
    float ax = 0.f, ay = 0.f;
    int j = 0;
    for (; j + 3 < n; j += 4) {
        int t0 = __ldg(&g_csr[beg + j + 0]);
        int t1 = __ldg(&g_csr[beg + j + 1]);
        int t2 = __ldg(&g_csr[beg + j + 2]);
        int t3 = __ldg(&g_csr[beg + j + 3]);
        float2 v0 = __half22float2(*(const __half2*)&g_h_task[t0 * 64 + lane * 2]);
        float2 v1 = __half22float2(*(const __half2*)&g_h_task[t1 * 64 + lane * 2]);
        float2 v2 = __half22float2(*(const __half2*)&g_h_task[t2 * 64 + lane * 2]);
        float2 v3 = __half22float2(*(const __half2*)&g_h_task[t3 * 64 + lane * 2]);
        ax += (v0.x + v1.x) + (v2.x + v3.x);
        ay += (v0.y + v1.y) + (v2.y + v3.y);
    }
    for (; j < n; j++) {
        int t = __ldg(&g_csr[beg + j]);
        float2 v = __half22float2(*(const __half2*)&g_h_task[t * 64 + lane * 2]);
        ax += v.x;
        ay += v.y;
    }
    float inv = (n > 0) ? 1.0f / (float)n : 0.f;
    float2 o;
    o.x = ax * inv;
    o.y = ay * inv;
    *(float2*)&out[(size_t)gw * 64 + lane * 2] = o;
}

// ---------------- launch ----------------
extern "C" void kernel_launch(void* const* d_in, const int* in_sizes, int n_in,
                              void* d_out, int out_size) {
    const float* feat_ret  = (const float*)d_in[0];
    const float* feat_dram = (const float*)d_in[1];
    const float* feat_link = (const float*)d_in[2];
    const float* W_ret   = (const float*)d_in[3];
    const float* b_ret   = (const float*)d_in[4];
    const float* W_dram  = (const float*)d_in[5];
    const float* b_dram  = (const float*)d_in[6];
    const float* W_link  = (const float*)d_in[7];
    const float* b_link  = (const float*)d_in[8];
    const float* W_task  = (const float*)d_in[9];
    const float* b_task  = (const float*)d_in[10];
    const int* task_ret  = (const int*)d_in[11];
    const int* mod_ret   = (const int*)d_in[12];
    const int* task_dram = (const int*)d_in[13];
    const int* mod_dram  = (const int*)d_in[14];
    const int* task_link = (const int*)d_in[15];
    const int* mod_link  = (const int*)d_in[16];
    float* out = (float*)d_out;

    const int TPB = 256;
    const int NE = E_LINK + E_RET + E_DRAM;  // 3,250,000
    const int smem_task = 64 * 192 * 4 + 64 * 97 * 8 + 192 * 8 + 192 * 4 + 192 * 4;
    cudaFuncSetAttribute(k_task, cudaFuncAttributeMaxDynamicSharedMemorySize, smem_task);

    k_init<<<(N_LINKN + TPB - 1) / TPB, TPB>>>();

    k_sum<<<(NE + TPB - 1) / TPB, TPB>>>(feat_link, mod_link,
                                         feat_ret,  mod_ret,
                                         feat_dram, mod_dram);

    k_scan<<<SCAN_NBLK, 256>>>();

    k_mm<<<(NE + TPB - 1) / TPB, TPB>>>(mod_link, task_link,
                                        mod_ret,  task_ret,
                                        mod_dram, task_dram);

    k_task<<<(N_TASK + 63) / 64, 512, smem_task>>>(W_ret, b_ret, W_dram, b_dram,
                                                   W_link, b_link, W_task, b_task);

    k_linkmean<<<(N_LINKN * 32 + TPB - 1) / TPB, TPB>>>(out);
}

// round 14
// speedup vs baseline: 1.0506x; 1.0204x over previous
#include <cuda_runtime.h>
#include <cuda_fp16.h>

#define N_TASK 50000
#define N_RET  20000
#define N_DRAM 5000
#define N_LINKN 100000
#define E_RET  1000000
#define E_DRAM 250000
#define E_LINK 2000000
#define HD 64
#define SCAN_NBLK 98   /* ceil(100000/1024) */

// ---------------- device scratch ----------------
__device__ float    g_s_ret[N_RET];
__device__ float    g_s_dram[N_DRAM];
__device__ float2   g_sc_link[N_LINKN];   // (sum, count) -> after scan: (sum, offs-bits)
__device__ uint2    g_mm[3 * N_TASK];     // (max_enc, min_enc) per (etype, task)
__device__ __half   g_h_task[N_TASK * HD];
__device__ int      g_cnt[N_LINKN];
__device__ int      g_offs[N_LINKN];
__device__ int      g_rank[E_LINK];       // edge's rank within its module
__device__ int      g_csr[E_LINK];
__device__ int      g_part[128];
__device__ int      g_done;

// order-preserving float<->uint encoding (all real floats encode > 0)
__device__ __forceinline__ unsigned encf(float f) {
    unsigned u = __float_as_uint(f);
    return (u & 0x80000000u) ? ~u : (u | 0x80000000u);
}
__device__ __forceinline__ float decf(unsigned u) {
    return __uint_as_float((u & 0x80000000u) ? (u & 0x7FFFFFFFu) : ~u);
}

__device__ __forceinline__ float tanh_fast(float x) {
    float y;
    asm("tanh.approx.f32 %0, %1;" : "=f"(y) : "f"(x));
    return y;
}

// half2 (2 consecutive k-weights) -> packed f32x2 operand
__device__ __forceinline__ unsigned long long h2_to_f32x2(__half2 h) {
    float2 f = __half22float2(h);
    unsigned long long r;
    asm("mov.b64 %0, {%1, %2};" : "=l"(r) : "f"(f.x), "f"(f.y));
    return r;
}

// ---------------- init ----------------
__global__ void k_init() {
    int i = blockIdx.x * blockDim.x + threadIdx.x;
    if (i == 0) g_done = 0;
    if (i < N_RET)  g_s_ret[i]  = 0.f;
    if (i < N_DRAM) g_s_dram[i] = 0.f;
    if (i < N_LINKN) g_sc_link[i] = make_float2(0.f, 0.f);
    if (i < N_TASK) {
#pragma unroll
        for (int et = 0; et < 3; et++)
            g_mm[et * N_TASK + i] = make_uint2(0u, 0xFFFFFFFFu);
    }
}

// ---------------- fused segment sums: 1 edge / thread ----------------
__global__ void k_sum(const float* __restrict__ fl, const int* __restrict__ ml,
                      const float* __restrict__ fr, const int* __restrict__ mr,
                      const float* __restrict__ fd, const int* __restrict__ md) {
    int i = blockIdx.x * blockDim.x + threadIdx.x;
    if (i < E_LINK) {
        int m = __ldg(&ml[i]);
        float2 old = atomicAdd(&g_sc_link[m], make_float2(__ldg(&fl[i]), 1.0f));
        g_rank[i] = (int)old.y;           // this edge's rank within module m
    } else if (i < E_LINK + E_RET) {
        int j = i - E_LINK;
        atomicAdd(&g_s_ret[__ldg(&mr[j])], __ldg(&fr[j]));
    } else if (i < E_LINK + E_RET + E_DRAM) {
        int j = i - E_LINK - E_RET;
        atomicAdd(&g_s_dram[__ldg(&md[j])], __ldg(&fd[j]));
    }
}

// ---------------- single-kernel scan: publish partial, spin-join, resume ---
// grid = 98 blocks < 148 SMs -> all co-resident in wave 1 -> spin is safe.
__global__ void k_scan() {
    __shared__ int sh[256];
    int b = blockIdx.x, tid = threadIdx.x;
    int i = b * 1024 + tid * 4;

    int c0 = 0, c1 = 0, c2 = 0, c3 = 0, s = 0;
    if (i < N_LINKN) {
        float4 a = *(const float4*)&g_sc_link[i];
        float4 d = *(const float4*)&g_sc_link[i + 2];
        c0 = (int)a.y; c1 = (int)a.w; c2 = (int)d.y; c3 = (int)d.w;
        s = c0 + c1 + c2 + c3;
    }

    sh[tid] = s;
    __syncthreads();
    for (int off = 1; off < 256; off <<= 1) {
        int u = (tid >= off) ? sh[tid - off] : 0;
        __syncthreads();
        sh[tid] += u;
        __syncthreads();
    }
    int incl = sh[tid];
    int blk_total = sh[255];

    if (tid == 0) {
        g_part[b] = blk_total;
        __threadfence();
        atomicAdd(&g_done, 1);
        while (*(volatile int*)&g_done < SCAN_NBLK) { }
    }
    __syncthreads();

    sh[tid] = (tid < b) ? ((volatile int*)g_part)[tid] : 0;
    __syncthreads();
    for (int off = 128; off > 0; off >>= 1) {
        if (tid < off) sh[tid] += sh[tid + off];
        __syncthreads();
    }
    int base = sh[0];

    int run = base + incl - s;
    if (i < N_LINKN) {
        int4 o;
        o.x = run;
        o.y = run + c0;
        o.z = o.y + c1;
        o.w = o.z + c2;
        *(int4*)&g_offs[i] = o;
        *(int4*)&g_cnt[i]  = make_int4(c0, c1, c2, c3);
        int2* scl = (int2*)g_sc_link;
        scl[i + 0].y = o.x;
        scl[i + 1].y = o.y;
        scl[i + 2].y = o.z;
        scl[i + 3].y = o.w;
    }
}

// ---------------- fused per-task min/max (link branch also scatters CSR) --
__global__ void k_mm(const int* __restrict__ ml, const int* __restrict__ tl,
                     const int* __restrict__ mr, const int* __restrict__ tr,
                     const int* __restrict__ md, const int* __restrict__ td) {
    int i = blockIdx.x * blockDim.x + threadIdx.x;
    if (i < E_LINK) {
        int m = __ldg(&ml[i]);
        int t = __ldg(&tl[i]);
        float2 sc = *(const float2*)&g_sc_link[m];   // one 8B scattered load
        unsigned k = encf(sc.x);
        atomicMax(&g_mm[2 * N_TASK + t].x, k);
        atomicMin(&g_mm[2 * N_TASK + t].y, k);
        int p = __float_as_int(sc.y) + __ldg(&g_rank[i]);
        g_csr[p] = t;
    } else if (i < E_LINK + E_RET) {
        int j = i - E_LINK;
        unsigned k = encf(g_s_ret[__ldg(&mr[j])]);
        int t = __ldg(&tr[j]);
        atomicMax(&g_mm[0 * N_TASK + t].x, k);
        atomicMin(&g_mm[0 * N_TASK + t].y, k);
    } else if (i < E_LINK + E_RET + E_DRAM) {
        int j = i - E_LINK - E_RET;
        unsigned k = encf(g_s_dram[__ldg(&md[j])]);
        int t = __ldg(&td[j]);
        atomicMax(&g_mm[1 * N_TASK + t].x, k);
        atomicMin(&g_mm[1 * N_TASK + t].y, k);
    }
}

// ---------------- task update: tanh(v @ Wtask^T + b), f32x2 FFMA ----------
// 256 threads, tile 64 tasks x 64 cols. Thread (lane tx, warp ty):
// columns tx, tx+32; tasks t0 = ty*8. W staged in smem as fp16 pairs:
// smem 75.3KB -> 3 blocks/SM (24 warps). w-loads: LDS.32 (4B aligned,
// odd word-stride 97 -> conflict-free).
__global__ void k_task(const float* __restrict__ Wret,  const float* __restrict__ bret,
                       const float* __restrict__ Wdram, const float* __restrict__ bdram,
                       const float* __restrict__ Wlink, const float* __restrict__ blink,
                       const float* __restrict__ Wtask, const float* __restrict__ btask) {
    extern __shared__ float sh[];
    float*   sV   = sh;                                    // 12288 f32
    __half2* sW2h = (__half2*)(sh + 64 * 192);             // 64*97 half2 (padded)
    uint2*   sMM  = (uint2*)(sh + 64 * 192 + 64 * 97);     // 192 uint2
    float*   sWe  = (float*)(sMM + 192);                   // 192 f32
    float*   sBe  = sWe + 192;                             // 192 f32

    int tb = blockIdx.x * 64;
    int tid = threadIdx.x;

    if (tid < 192) {
        int et = tid >> 6, hh = tid & 63;
        const float* We = (et == 0) ? Wret : (et == 1) ? Wdram : Wlink;
        const float* be = (et == 0) ? bret : (et == 1) ? bdram : blink;
        sWe[tid] = We[hh];
        sBe[tid] = be[hh];
    }
    for (int idx = tid; idx < 64 * 3; idx += 256) {
        int tl = idx / 3, et = idx - tl * 3;
        int t = tb + tl;
        sMM[tl * 3 + et] = (t < N_TASK) ? g_mm[et * N_TASK + t]
                                        : make_uint2(0u, 0xFFFFFFFFu);
    }
    for (int idx = tid; idx < 64 * 96; idx += 256) {
        int h = idx / 96, kp = idx - h * 96;
        float2 w = *(const float2*)&Wtask[h * 192 + 2 * kp];
        sW2h[h * 97 + kp] = __float22half2_rn(w);
    }
    __syncthreads();

    for (int idx = tid; idx < 64 * 192; idx += 256) {
        int tl = idx / 192, k = idx - tl * 192;
        int et = k >> 6, h = k & 63;
        float v = 0.f;
        uint2 mm = sMM[tl * 3 + et];
        if (mm.x != 0u) {
            float w = sWe[et * 64 + h];
            float sv = (w >= 0.f) ? decf(mm.x) : decf(mm.y);
            v = tanh_fast(fmaf(w, sv, sBe[et * 64 + h]));
        }
        sV[idx] = v;
    }
    __syncthreads();

    int tx = tid & 31, ty = tid >> 5;
    int t0 = ty * 8;

    unsigned long long acc0[8], acc1[8];
#pragma unroll
    for (int i = 0; i < 8; i++) { acc0[i] = 0ull; acc1[i] = 0ull; }

    const __half2* w0row = sW2h + tx * 97;
    const __half2* w1row = sW2h + (tx + 32) * 97;
    const float*   vb    = sV + t0 * 192;

#pragma unroll 4
    for (int kp = 0; kp < 96; kp += 2) {
        // 4B LDS.32 each: always aligned; odd stride 97 -> conflict-free
        unsigned long long wa0 = h2_to_f32x2(w0row[kp]);
        unsigned long long wa1 = h2_to_f32x2(w0row[kp + 1]);
        unsigned long long wb0 = h2_to_f32x2(w1row[kp]);
        unsigned long long wb1 = h2_to_f32x2(w1row[kp + 1]);
#pragma unroll
        for (int i = 0; i < 8; i++) {
            ulonglong2 v = *(const ulonglong2*)(vb + i * 192 + 2 * kp);
            asm("fma.rn.f32x2 %0, %1, %2, %0;" : "+l"(acc0[i]) : "l"(v.x), "l"(wa0));
            asm("fma.rn.f32x2 %0, %1, %2, %0;" : "+l"(acc0[i]) : "l"(v.y), "l"(wa1));
            asm("fma.rn.f32x2 %0, %1, %2, %0;" : "+l"(acc1[i]) : "l"(v.x), "l"(wb0));
            asm("fma.rn.f32x2 %0, %1, %2, %0;" : "+l"(acc1[i]) : "l"(v.y), "l"(wb1));
        }
    }

    float bh0 = btask[tx], bh1 = btask[tx + 32];
#pragma unroll
    for (int i = 0; i < 8; i++) {
        int t = tb + t0 + i;
        if (t < N_TASK) {
            float lo, hi;
            asm("mov.b64 {%0, %1}, %2;" : "=f"(lo), "=f"(hi) : "l"(acc0[i]));
            g_h_task[t * 64 + tx] = __float2half(tanh_fast(lo + hi + bh0));
            asm("mov.b64 {%0, %1}, %2;" : "=f"(lo), "=f"(hi) : "l"(acc1[i]));
            g_h_task[t * 64 + tx + 32] = __float2half(tanh_fast(lo + hi + bh1));
        }
    }
}

// ---------------- link mean: warp per link node, CSR gather (fp16 h) ------
__global__ void k_linkmean(float* __restrict__ out) {
    int gw = (blockIdx.x * blockDim.x + threadIdx.x) >> 5;
    if (gw >= N_LINKN) return;
    int lane = threadIdx.x & 31;
    int beg = g_offs[gw];
    int n = g_cnt[gw];
    float ax = 0.f, ay = 0.f;
    int j = 0;
    for (; j + 3 < n; j += 4) {
        int t0 = __ldg(&g_csr[beg + j + 0]);
        int t1 = __ldg(&g_csr[beg + j + 1]);
        int t2 = __ldg(&g_csr[beg + j + 2]);
        int t3 = __ldg(&g_csr[beg + j + 3]);
        float2 v0 = __half22float2(*(const __half2*)&g_h_task[t0 * 64 + lane * 2]);
        float2 v1 = __half22float2(*(const __half2*)&g_h_task[t1 * 64 + lane * 2]);
        float2 v2 = __half22float2(*(const __half2*)&g_h_task[t2 * 64 + lane * 2]);
        float2 v3 = __half22float2(*(const __half2*)&g_h_task[t3 * 64 + lane * 2]);
        ax += (v0.x + v1.x) + (v2.x + v3.x);
        ay += (v0.y + v1.y) + (v2.y + v3.y);
    }
    for (; j < n; j++) {
        int t = __ldg(&g_csr[beg + j]);
        float2 v = __half22float2(*(const __half2*)&g_h_task[t * 64 + lane * 2]);
        ax += v.x;
        ay += v.y;
    }
    float inv = (n > 0) ? 1.0f / (float)n : 0.f;
    float2 o;
    o.x = ax * inv;
    o.y = ay * inv;
    *(float2*)&out[(size_t)gw * 64 + lane * 2] = o;
}

// ---------------- launch ----------------
extern "C" void kernel_launch(void* const* d_in, const int* in_sizes, int n_in,
                              void* d_out, int out_size) {
    const float* feat_ret  = (const float*)d_in[0];
    const float* feat_dram = (const float*)d_in[1];
    const float* feat_link = (const float*)d_in[2];
    const float* W_ret   = (const float*)d_in[3];
    const float* b_ret   = (const float*)d_in[4];
    const float* W_dram  = (const float*)d_in[5];
    const float* b_dram  = (const float*)d_in[6];
    const float* W_link  = (const float*)d_in[7];
    const float* b_link  = (const float*)d_in[8];
    const float* W_task  = (const float*)d_in[9];
    const float* b_task  = (const float*)d_in[10];
    const int* task_ret  = (const int*)d_in[11];
    const int* mod_ret   = (const int*)d_in[12];
    const int* task_dram = (const int*)d_in[13];
    const int* mod_dram  = (const int*)d_in[14];
    const int* task_link = (const int*)d_in[15];
    const int* mod_link  = (const int*)d_in[16];
    float* out = (float*)d_out;

    const int TPB = 256;
    const int NE = E_LINK + E_RET + E_DRAM;  // 3,250,000
    // sV(49152) + sW2h(24832) + sMM(1536) + sWe(768) + sBe(768) = 77056 B
    const int smem_task = 64 * 192 * 4 + 64 * 97 * 4 + 192 * 8 + 192 * 4 + 192 * 4;
    cudaFuncSetAttribute(k_task, cudaFuncAttributeMaxDynamicSharedMemorySize, smem_task);

    k_init<<<(N_LINKN + TPB - 1) / TPB, TPB>>>();

    k_sum<<<(NE + TPB - 1) / TPB, TPB>>>(feat_link, mod_link,
                                         feat_ret,  mod_ret,
                                         feat_dram, mod_dram);

    k_scan<<<SCAN_NBLK, 256>>>();

    k_mm<<<(NE + TPB - 1) / TPB, TPB>>>(mod_link, task_link,
                                        mod_ret,  task_ret,
                                        mod_dram, task_dram);

    k_task<<<(N_TASK + 63) / 64, TPB, smem_task>>>(W_ret, b_ret, W_dram, b_dram,
                                                   W_link, b_link, W_task, b_task);

    k_linkmean<<<(N_LINKN * 32 + TPB - 1) / TPB, TPB>>>(out);
}

// round 15
// speedup vs baseline: 1.1333x; 1.0787x over previous
#include <cuda_runtime.h>
#include <cuda_fp16.h>

#define N_TASK 50000
#define N_RET  20000
#define N_DRAM 5000
#define N_LINKN 100000
#define E_RET  1000000
#define E_DRAM 250000
#define E_LINK 2000000
#define HD 64
#define SCAN_NBLK 98   /* ceil(100000/1024) */

// ---------------- device scratch ----------------
__device__ float    g_s_ret[N_RET];
__device__ float    g_s_dram[N_DRAM];
__device__ float2   g_sc_link[N_LINKN];   // (sum, count) -> after scan: (sum, offs-bits)
__device__ uint2    g_mm[3 * N_TASK];     // (max_enc, min_enc) per (etype, task)
__device__ __half   g_h_task[N_TASK * HD];
__device__ int      g_cnt[N_LINKN];
__device__ int      g_offs[N_LINKN];
__device__ int      g_rank[E_LINK];       // edge's rank within its module
__device__ int      g_csr[E_LINK];
__device__ int      g_part[128];
__device__ int      g_done;

// order-preserving float<->uint encoding (all real floats encode > 0)
__device__ __forceinline__ unsigned encf(float f) {
    unsigned u = __float_as_uint(f);
    return (u & 0x80000000u) ? ~u : (u | 0x80000000u);
}
__device__ __forceinline__ float decf(unsigned u) {
    return __uint_as_float((u & 0x80000000u) ? (u & 0x7FFFFFFFu) : ~u);
}

__device__ __forceinline__ float tanh_fast(float x) {
    float y;
    asm("tanh.approx.f32 %0, %1;" : "=f"(y) : "f"(x));
    return y;
}

__device__ __forceinline__ unsigned f2tf32(float f) {
    unsigned r;
    asm("cvt.rna.tf32.f32 %0, %1;" : "=r"(r) : "f"(f));
    return r;
}

// ---------------- init ----------------
__global__ void k_init() {
    int i = blockIdx.x * blockDim.x + threadIdx.x;
    if (i == 0) g_done = 0;
    if (i < N_RET)  g_s_ret[i]  = 0.f;
    if (i < N_DRAM) g_s_dram[i] = 0.f;
    if (i < N_LINKN) g_sc_link[i] = make_float2(0.f, 0.f);
    if (i < N_TASK) {
#pragma unroll
        for (int et = 0; et < 3; et++)
            g_mm[et * N_TASK + i] = make_uint2(0u, 0xFFFFFFFFu);
    }
}

// ---------------- fused segment sums: 1 edge / thread ----------------
__global__ void k_sum(const float* __restrict__ fl, const int* __restrict__ ml,
                      const float* __restrict__ fr, const int* __restrict__ mr,
                      const float* __restrict__ fd, const int* __restrict__ md) {
    int i = blockIdx.x * blockDim.x + threadIdx.x;
    if (i < E_LINK) {
        int m = __ldg(&ml[i]);
        float2 old = atomicAdd(&g_sc_link[m], make_float2(__ldg(&fl[i]), 1.0f));
        g_rank[i] = (int)old.y;           // this edge's rank within module m
    } else if (i < E_LINK + E_RET) {
        int j = i - E_LINK;
        atomicAdd(&g_s_ret[__ldg(&mr[j])], __ldg(&fr[j]));
    } else if (i < E_LINK + E_RET + E_DRAM) {
        int j = i - E_LINK - E_RET;
        atomicAdd(&g_s_dram[__ldg(&md[j])], __ldg(&fd[j]));
    }
}

// ---------------- single-kernel scan: publish partial, spin-join, resume ---
// grid = 98 blocks < 148 SMs -> all co-resident in wave 1 -> spin is safe.
__global__ void k_scan() {
    __shared__ int sh[256];
    int b = blockIdx.x, tid = threadIdx.x;
    int i = b * 1024 + tid * 4;

    int c0 = 0, c1 = 0, c2 = 0, c3 = 0, s = 0;
    if (i < N_LINKN) {
        float4 a = *(const float4*)&g_sc_link[i];
        float4 d = *(const float4*)&g_sc_link[i + 2];
        c0 = (int)a.y; c1 = (int)a.w; c2 = (int)d.y; c3 = (int)d.w;
        s = c0 + c1 + c2 + c3;
    }

    sh[tid] = s;
    __syncthreads();
    for (int off = 1; off < 256; off <<= 1) {
        int u = (tid >= off) ? sh[tid - off] : 0;
        __syncthreads();
        sh[tid] += u;
        __syncthreads();
    }
    int incl = sh[tid];
    int blk_total = sh[255];

    if (tid == 0) {
        g_part[b] = blk_total;
        __threadfence();
        atomicAdd(&g_done, 1);
        while (*(volatile int*)&g_done < SCAN_NBLK) { }
    }
    __syncthreads();

    sh[tid] = (tid < b) ? ((volatile int*)g_part)[tid] : 0;
    __syncthreads();
    for (int off = 128; off > 0; off >>= 1) {
        if (tid < off) sh[tid] += sh[tid + off];
        __syncthreads();
    }
    int base = sh[0];

    int run = base + incl - s;
    if (i < N_LINKN) {
        int4 o;
        o.x = run;
        o.y = run + c0;
        o.z = o.y + c1;
        o.w = o.z + c2;
        *(int4*)&g_offs[i] = o;
        *(int4*)&g_cnt[i]  = make_int4(c0, c1, c2, c3);
        int2* scl = (int2*)g_sc_link;
        scl[i + 0].y = o.x;
        scl[i + 1].y = o.y;
        scl[i + 2].y = o.z;
        scl[i + 3].y = o.w;
    }
}

// ---------------- fused per-task min/max (link branch also scatters CSR) --
__global__ void k_mm(const int* __restrict__ ml, const int* __restrict__ tl,
                     const int* __restrict__ mr, const int* __restrict__ tr,
                     const int* __restrict__ md, const int* __restrict__ td) {
    int i = blockIdx.x * blockDim.x + threadIdx.x;
    if (i < E_LINK) {
        int m = __ldg(&ml[i]);
        int t = __ldg(&tl[i]);
        float2 sc = *(const float2*)&g_sc_link[m];   // one 8B scattered load
        unsigned k = encf(sc.x);
        atomicMax(&g_mm[2 * N_TASK + t].x, k);
        atomicMin(&g_mm[2 * N_TASK + t].y, k);
        int p = __float_as_int(sc.y) + __ldg(&g_rank[i]);
        g_csr[p] = t;
    } else if (i < E_LINK + E_RET) {
        int j = i - E_LINK;
        unsigned k = encf(g_s_ret[__ldg(&mr[j])]);
        int t = __ldg(&tr[j]);
        atomicMax(&g_mm[0 * N_TASK + t].x, k);
        atomicMin(&g_mm[0 * N_TASK + t].y, k);
    } else if (i < E_LINK + E_RET + E_DRAM) {
        int j = i - E_LINK - E_RET;
        unsigned k = encf(g_s_dram[__ldg(&md[j])]);
        int t = __ldg(&td[j]);
        atomicMax(&g_mm[1 * N_TASK + t].x, k);
        atomicMin(&g_mm[1 * N_TASK + t].y, k);
    }
}

// ---------------- task update: tanh(v @ Wtask^T + b) via tf32 mma.sync ----
// 256 threads (8 warps), tile 64 tasks x 64 cols, K=192 (24 k-steps of 8).
// Warp wid: m-tile mi = wid&3 (16 tasks), n-half nh = wid>>2 (4 n-tiles of 8).
// sV/sW staged as tf32 bits, word-stride 196 (mod 32 = 4 -> conflict-free
// fragment gathers: bank = 4*g + tg, all 32 distinct).
__global__ void k_task(const float* __restrict__ Wret,  const float* __restrict__ bret,
                       const float* __restrict__ Wdram, const float* __restrict__ bdram,
                       const float* __restrict__ Wlink, const float* __restrict__ blink,
                       const float* __restrict__ Wtask, const float* __restrict__ btask) {
    extern __shared__ unsigned smem_u[];
    unsigned* sV  = smem_u;                  // [64][196] tf32 bits of v (A, row-major)
    unsigned* sW  = smem_u + 64 * 196;       // [64][196] tf32 bits of W (B col-major: row h=n, col k)
    uint2*    sMM = (uint2*)(sW + 64 * 196); // 192 uint2
    float*    sWe = (float*)(sMM + 192);     // 192 f32
    float*    sBe = sWe + 192;               // 192 f32

    int tb = blockIdx.x * 64;
    int tid = threadIdx.x;

    if (tid < 192) {
        int et = tid >> 6, hh = tid & 63;
        const float* We = (et == 0) ? Wret : (et == 1) ? Wdram : Wlink;
        const float* be = (et == 0) ? bret : (et == 1) ? bdram : blink;
        sWe[tid] = We[hh];
        sBe[tid] = be[hh];
    }
    for (int idx = tid; idx < 64 * 3; idx += 256) {
        int tl = idx / 3, et = idx - tl * 3;
        int t = tb + tl;
        sMM[tl * 3 + et] = (t < N_TASK) ? g_mm[et * N_TASK + t]
                                        : make_uint2(0u, 0xFFFFFFFFu);
    }
    // stage Wtask as tf32: sW[h*196 + k]
    for (int idx = tid; idx < 64 * 192; idx += 256) {
        int h = idx / 192, k = idx - h * 192;
        sW[h * 196 + k] = f2tf32(Wtask[idx]);
    }
    __syncthreads();

    // build v (A matrix): sV[tl*196 + k] = tf32(tanh(...)) via monotone trick
    for (int idx = tid; idx < 64 * 192; idx += 256) {
        int tl = idx / 192, k = idx - tl * 192;
        int et = k >> 6, h = k & 63;
        float v = 0.f;
        uint2 mm = sMM[tl * 3 + et];
        if (mm.x != 0u) {
            float w = sWe[et * 64 + h];
            float sv = (w >= 0.f) ? decf(mm.x) : decf(mm.y);
            v = tanh_fast(fmaf(w, sv, sBe[et * 64 + h]));
        }
        sV[tl * 196 + k] = f2tf32(v);
    }
    __syncthreads();

    int lane = tid & 31, wid = tid >> 5;
    int g = lane >> 2, tg = lane & 3;
    int mi = wid & 3, nh = wid >> 2;

    float acc[4][4];
#pragma unroll
    for (int t = 0; t < 4; t++)
#pragma unroll
        for (int c = 0; c < 4; c++) acc[t][c] = 0.f;

    const unsigned* Arow0 = sV + (mi * 16 + g) * 196 + tg;
    const unsigned* Arow8 = Arow0 + 8 * 196;

#pragma unroll 4
    for (int ks = 0; ks < 24; ks++) {
        int k0 = ks * 8;
        unsigned a0 = Arow0[k0];
        unsigned a1 = Arow8[k0];
        unsigned a2 = Arow0[k0 + 4];
        unsigned a3 = Arow8[k0 + 4];
#pragma unroll
        for (int t = 0; t < 4; t++) {
            int n = (nh * 4 + t) * 8 + g;
            unsigned b0 = sW[n * 196 + k0 + tg];
            unsigned b1 = sW[n * 196 + k0 + tg + 4];
            asm volatile(
                "mma.sync.aligned.m16n8k8.row.col.f32.tf32.tf32.f32 "
                "{%0,%1,%2,%3}, {%4,%5,%6,%7}, {%8,%9}, {%0,%1,%2,%3};"
                : "+f"(acc[t][0]), "+f"(acc[t][1]), "+f"(acc[t][2]), "+f"(acc[t][3])
                : "r"(a0), "r"(a1), "r"(a2), "r"(a3), "r"(b0), "r"(b1));
        }
    }

    // epilogue: c0/c1 -> (task, col..col+1); c2/c3 -> (task+8, col..col+1)
#pragma unroll
    for (int t = 0; t < 4; t++) {
        int col = (nh * 4 + t) * 8 + 2 * tg;
        float b0v = btask[col], b1v = btask[col + 1];
        int task0 = tb + mi * 16 + g;
        int task1 = task0 + 8;
        if (task0 < N_TASK) {
            __half2 o = __floats2half2_rn(tanh_fast(acc[t][0] + b0v),
                                          tanh_fast(acc[t][1] + b1v));
            *(__half2*)&g_h_task[task0 * 64 + col] = o;
        }
        if (task1 < N_TASK) {
            __half2 o = __floats2half2_rn(tanh_fast(acc[t][2] + b0v),
                                          tanh_fast(acc[t][3] + b1v));
            *(__half2*)&g_h_task[task1 * 64 + col] = o;
        }
    }
}

// ---------------- link mean: warp per link node, CSR gather (fp16 h) ------
__global__ void k_linkmean(float* __restrict__ out) {
    int gw = (blockIdx.x * blockDim.x + threadIdx.x) >> 5;
    if (gw >= N_LINKN) return;
    int lane = threadIdx.x & 31;
    int beg = g_offs[gw];
    int n = g_cnt[gw];
    float ax = 0.f, ay = 0.f;
    int j = 0;
    for (; j + 3 < n; j += 4) {
        int t0 = __ldg(&g_csr[beg + j + 0]);
        int t1 = __ldg(&g_csr[beg + j + 1]);
        int t2 = __ldg(&g_csr[beg + j + 2]);
        int t3 = __ldg(&g_csr[beg + j + 3]);
        float2 v0 = __half22float2(*(const __half2*)&g_h_task[t0 * 64 + lane * 2]);
        float2 v1 = __half22float2(*(const __half2*)&g_h_task[t1 * 64 + lane * 2]);
        float2 v2 = __half22float2(*(const __half2*)&g_h_task[t2 * 64 + lane * 2]);
        float2 v3 = __half22float2(*(const __half2*)&g_h_task[t3 * 64 + lane * 2]);
        ax += (v0.x + v1.x) + (v2.x + v3.x);
        ay += (v0.y + v1.y) + (v2.y + v3.y);
    }
    for (; j < n; j++) {
        int t = __ldg(&g_csr[beg + j]);
        float2 v = __half22float2(*(const __half2*)&g_h_task[t * 64 + lane * 2]);
        ax += v.x;
        ay += v.y;
    }
    float inv = (n > 0) ? 1.0f / (float)n : 0.f;
    float2 o;
    o.x = ax * inv;
    o.y = ay * inv;
    *(float2*)&out[(size_t)gw * 64 + lane * 2] = o;
}

// ---------------- launch ----------------
extern "C" void kernel_launch(void* const* d_in, const int* in_sizes, int n_in,
                              void* d_out, int out_size) {
    const float* feat_ret  = (const float*)d_in[0];
    const float* feat_dram = (const float*)d_in[1];
    const float* feat_link = (const float*)d_in[2];
    const float* W_ret   = (const float*)d_in[3];
    const float* b_ret   = (const float*)d_in[4];
    const float* W_dram  = (const float*)d_in[5];
    const float* b_dram  = (const float*)d_in[6];
    const float* W_link  = (const float*)d_in[7];
    const float* b_link  = (const float*)d_in[8];
    const float* W_task  = (const float*)d_in[9];
    const float* b_task  = (const float*)d_in[10];
    const int* task_ret  = (const int*)d_in[11];
    const int* mod_ret   = (const int*)d_in[12];
    const int* task_dram = (const int*)d_in[13];
    const int* mod_dram  = (const int*)d_in[14];
    const int* task_link = (const int*)d_in[15];
    const int* mod_link  = (const int*)d_in[16];
    float* out = (float*)d_out;

    const int TPB = 256;
    const int NE = E_LINK + E_RET + E_DRAM;  // 3,250,000
    // sV(50176) + sW(50176) + sMM(1536) + sWe(768) + sBe(768) = 103424 B
    const int smem_task = 64 * 196 * 4 * 2 + 192 * 8 + 192 * 4 + 192 * 4;
    cudaFuncSetAttribute(k_task, cudaFuncAttributeMaxDynamicSharedMemorySize, smem_task);

    k_init<<<(N_LINKN + TPB - 1) / TPB, TPB>>>();

    k_sum<<<(NE + TPB - 1) / TPB, TPB>>>(feat_link, mod_link,
                                         feat_ret,  mod_ret,
                                         feat_dram, mod_dram);

    k_scan<<<SCAN_NBLK, 256>>>();

    k_mm<<<(NE + TPB - 1) / TPB, TPB>>>(mod_link, task_link,
                                        mod_ret,  task_ret,
                                        mod_dram, task_dram);

    k_task<<<(N_TASK + 63) / 64, TPB, smem_task>>>(W_ret, b_ret, W_dram, b_dram,
                                                   W_link, b_link, W_task, b_task);

    k_linkmean<<<(N_LINKN * 32 + TPB - 1) / TPB, TPB>>>(out);
}

// round 17
// speedup vs baseline: 1.3021x; 1.1490x over previous
#include <cuda_runtime.h>
#include <cuda_fp16.h>

#define N_TASK 50000
#define N_RET  20000
#define N_DRAM 5000
#define N_LINKN 100000
#define E_RET  1000000
#define E_DRAM 250000
#define E_LINK 2000000
#define HD 64
#define SCAN_NBLK 98   /* ceil(100000/1024) */
#define NE_ALL (E_LINK + E_RET + E_DRAM)

// ---------------- device scratch ----------------
__device__ float    g_s_ret[N_RET];
__device__ float    g_s_dram[N_DRAM];
__device__ float2   g_sc_link[N_LINKN];   // (sum, count) -> after scan: (sum, offs-bits)
__device__ uint2    g_mm[3 * N_TASK];     // (max_enc, min_enc) per (etype, task)
__device__ __half   g_h_task[N_TASK * HD];
__device__ int      g_cnt[N_LINKN];
__device__ int      g_offs[N_LINKN];
__device__ int      g_rank[E_LINK];       // edge's rank within its module
__device__ int      g_csr[E_LINK];
__device__ int      g_part[128];
__device__ int      g_done;

// order-preserving float<->uint encoding (all real floats encode > 0)
__device__ __forceinline__ unsigned encf(float f) {
    unsigned u = __float_as_uint(f);
    return (u & 0x80000000u) ? ~u : (u | 0x80000000u);
}
__device__ __forceinline__ float decf(unsigned u) {
    return __uint_as_float((u & 0x80000000u) ? (u & 0x7FFFFFFFu) : ~u);
}

__device__ __forceinline__ float tanh_fast(float x) {
    float y;
    asm("tanh.approx.f32 %0, %1;" : "=f"(y) : "f"(x));
    return y;
}

__device__ __forceinline__ unsigned h2bits(__half2 h) {
    return *(unsigned*)&h;
}

// ---------------- init (g_mm init lives in k_sum tail) ----------------
__global__ void k_init() {
    int i = blockIdx.x * blockDim.x + threadIdx.x;
    if (i == 0) g_done = 0;
    if (i < N_RET)  g_s_ret[i]  = 0.f;
    if (i < N_DRAM) g_s_dram[i] = 0.f;
    if (i < N_LINKN) g_sc_link[i] = make_float2(0.f, 0.f);
}

// ---------------- fused segment sums + g_mm init: 1 edge / thread ---------
__global__ void k_sum(const float* __restrict__ fl, const int* __restrict__ ml,
                      const float* __restrict__ fr, const int* __restrict__ mr,
                      const float* __restrict__ fd, const int* __restrict__ md) {
    int i = blockIdx.x * blockDim.x + threadIdx.x;
    if (i < E_LINK) {
        int m = __ldg(&ml[i]);
        float2 old = atomicAdd(&g_sc_link[m], make_float2(__ldg(&fl[i]), 1.0f));
        g_rank[i] = (int)old.y;           // this edge's rank within module m
    } else if (i < E_LINK + E_RET) {
        int j = i - E_LINK;
        atomicAdd(&g_s_ret[__ldg(&mr[j])], __ldg(&fr[j]));
    } else if (i < NE_ALL) {
        int j = i - E_LINK - E_RET;
        atomicAdd(&g_s_dram[__ldg(&md[j])], __ldg(&fd[j]));
    } else if (i < NE_ALL + 3 * N_TASK) {
        g_mm[i - NE_ALL] = make_uint2(0u, 0xFFFFFFFFu);
    }
}

// ---------------- single-kernel scan: publish partial, spin-join, resume ---
// grid = 98 blocks < 148 SMs -> all co-resident in wave 1 -> spin is safe.
__global__ void k_scan() {
    __shared__ int sh[256];
    int b = blockIdx.x, tid = threadIdx.x;
    int i = b * 1024 + tid * 4;

    int c0 = 0, c1 = 0, c2 = 0, c3 = 0, s = 0;
    if (i < N_LINKN) {
        float4 a = *(const float4*)&g_sc_link[i];
        float4 d = *(const float4*)&g_sc_link[i + 2];
        c0 = (int)a.y; c1 = (int)a.w; c2 = (int)d.y; c3 = (int)d.w;
        s = c0 + c1 + c2 + c3;
    }

    sh[tid] = s;
    __syncthreads();
    for (int off = 1; off < 256; off <<= 1) {
        int u = (tid >= off) ? sh[tid - off] : 0;
        __syncthreads();
        sh[tid] += u;
        __syncthreads();
    }
    int incl = sh[tid];
    int blk_total = sh[255];

    if (tid == 0) {
        g_part[b] = blk_total;
        __threadfence();
        atomicAdd(&g_done, 1);
        while (*(volatile int*)&g_done < SCAN_NBLK) { }
    }
    __syncthreads();

    sh[tid] = (tid < b) ? ((volatile int*)g_part)[tid] : 0;
    __syncthreads();
    for (int off = 128; off > 0; off >>= 1) {
        if (tid < off) sh[tid] += sh[tid + off];
        __syncthreads();
    }
    int base = sh[0];

    int run = base + incl - s;
    if (i < N_LINKN) {
        int4 o;
        o.x = run;
        o.y = run + c0;
        o.z = o.y + c1;
        o.w = o.z + c2;
        *(int4*)&g_offs[i] = o;
        *(int4*)&g_cnt[i]  = make_int4(c0, c1, c2, c3);
        int2* scl = (int2*)g_sc_link;
        scl[i + 0].y = o.x;
        scl[i + 1].y = o.y;
        scl[i + 2].y = o.z;
        scl[i + 3].y = o.w;
    }
}

// ---------------- fused per-task min/max (link branch also scatters CSR) --
__global__ void k_mm(const int* __restrict__ ml, const int* __restrict__ tl,
                     const int* __restrict__ mr, const int* __restrict__ tr,
                     const int* __restrict__ md, const int* __restrict__ td) {
    int i = blockIdx.x * blockDim.x + threadIdx.x;
    if (i < E_LINK) {
        int m = __ldg(&ml[i]);
        int t = __ldg(&tl[i]);
        float2 sc = *(const float2*)&g_sc_link[m];   // one 8B scattered load
        unsigned k = encf(sc.x);
        atomicMax(&g_mm[2 * N_TASK + t].x, k);
        atomicMin(&g_mm[2 * N_TASK + t].y, k);
        int p = __float_as_int(sc.y) + __ldg(&g_rank[i]);
        g_csr[p] = t;
    } else if (i < E_LINK + E_RET) {
        int j = i - E_LINK;
        unsigned k = encf(g_s_ret[__ldg(&mr[j])]);
        int t = __ldg(&tr[j]);
        atomicMax(&g_mm[0 * N_TASK + t].x, k);
        atomicMin(&g_mm[0 * N_TASK + t].y, k);
    } else if (i < NE_ALL) {
        int j = i - E_LINK - E_RET;
        unsigned k = encf(g_s_dram[__ldg(&md[j])]);
        int t = __ldg(&td[j]);
        atomicMax(&g_mm[1 * N_TASK + t].x, k);
        atomicMin(&g_mm[1 * N_TASK + t].y, k);
    }
}

// ---------------- task update: tanh(v @ Wtask^T + b) via fp16 mma.sync ----
// 256 threads (8 warps), tile 64 tasks x 64 cols, K=192 (12 k-steps of 16).
// Warp wid: m-tile mi = wid&3 (16 tasks), n-half nh = wid>>2 (4 n-tiles of 8).
// sV/sW staged as half2 k-pairs, word-stride 100 (mod 32 = 4 -> conflict-free
// fragment gathers: bank = 4*g + tg). smem ~54KB -> 4 blocks/SM.
__global__ void k_task(const float* __restrict__ Wret,  const float* __restrict__ bret,
                       const float* __restrict__ Wdram, const float* __restrict__ bdram,
                       const float* __restrict__ Wlink, const float* __restrict__ blink,
                       const float* __restrict__ Wtask, const float* __restrict__ btask) {
    extern __shared__ unsigned smem_u[];
    unsigned* sV  = smem_u;                  // [64][100] half2 k-pairs of v (A row-major)
    unsigned* sW  = smem_u + 64 * 100;       // [64][100] half2 k-pairs of W (B: row h=n)
    uint2*    sMM = (uint2*)(sW + 64 * 100); // 192 uint2
    float*    sWe = (float*)(sMM + 192);     // 192 f32
    float*    sBe = sWe + 192;               // 192 f32

    int tb = blockIdx.x * 64;
    int tid = threadIdx.x;

    if (tid < 192) {
        int et = tid >> 6, hh = tid & 63;
        const float* We = (et == 0) ? Wret : (et == 1) ? Wdram : Wlink;
        const float* be = (et == 0) ? bret : (et == 1) ? bdram : blink;
        sWe[tid] = We[hh];
        sBe[tid] = be[hh];
    }
    for (int idx = tid; idx < 64 * 3; idx += 256) {
        int tl = idx / 3, et = idx - tl * 3;
        int t = tb + tl;
        sMM[tl * 3 + et] = (t < N_TASK) ? g_mm[et * N_TASK + t]
                                        : make_uint2(0u, 0xFFFFFFFFu);
    }
    // stage Wtask as half2 k-pairs: sW[h*100 + kp]
    for (int idx = tid; idx < 64 * 96; idx += 256) {
        int h = idx / 96, kp = idx - h * 96;
        float2 w = *(const float2*)&Wtask[h * 192 + 2 * kp];
        sW[h * 100 + kp] = h2bits(__float22half2_rn(w));
    }
    __syncthreads();

    // build v (A): pairs (k, k+1) share tl/et; one tanh.approx.f16x2 per pair
    for (int idx = tid; idx < 64 * 96; idx += 256) {
        int tl = idx / 96, kp = idx - tl * 96;
        int et = kp >> 5;           // k = 2*kp, et = k>>6
        int h = (kp & 31) * 2;
        unsigned out = 0u;
        uint2 mm = sMM[tl * 3 + et];
        if (mm.x != 0u) {
            float smax = decf(mm.x), smin = decf(mm.y);
            float w0 = sWe[et * 64 + h],     b0 = sBe[et * 64 + h];
            float w1 = sWe[et * 64 + h + 1], b1 = sBe[et * 64 + h + 1];
            float f0 = fmaf(w0, (w0 >= 0.f) ? smax : smin, b0);
            float f1 = fmaf(w1, (w1 >= 0.f) ? smax : smin, b1);
            unsigned hvu = h2bits(__floats2half2_rn(f0, f1));
            asm("tanh.approx.f16x2 %0, %1;" : "=r"(out) : "r"(hvu));
        }
        sV[tl * 100 + kp] = out;
    }
    __syncthreads();

    int lane = tid & 31, wid = tid >> 5;
    int g = lane >> 2, tg = lane & 3;
    int mi = wid & 3, nh = wid >> 2;

    float acc[4][4];
#pragma unroll
    for (int t = 0; t < 4; t++)
#pragma unroll
        for (int c = 0; c < 4; c++) acc[t][c] = 0.f;

    const unsigned* Arow0 = sV + (mi * 16 + g) * 100 + tg;
    const unsigned* Arow8 = Arow0 + 8 * 100;

#pragma unroll 4
    for (int ks = 0; ks < 12; ks++) {
        int k0 = ks * 8;                      // in half2 units (16 halves per step)
        unsigned a0 = Arow0[k0];              // (g,   2tg..2tg+1)
        unsigned a1 = Arow8[k0];              // (g+8, 2tg..2tg+1)
        unsigned a2 = Arow0[k0 + 4];          // (g,   8+2tg..)
        unsigned a3 = Arow8[k0 + 4];          // (g+8, 8+2tg..)
#pragma unroll
        for (int t = 0; t < 4; t++) {
            int n = (nh * 4 + t) * 8 + g;
            unsigned b0 = sW[n * 100 + k0 + tg];
            unsigned b1 = sW[n * 100 + k0 + tg + 4];
            asm volatile(
                "mma.sync.aligned.m16n8k16.row.col.f32.f16.f16.f32 "
                "{%0,%1,%2,%3}, {%4,%5,%6,%7}, {%8,%9}, {%0,%1,%2,%3};"
                : "+f"(acc[t][0]), "+f"(acc[t][1]), "+f"(acc[t][2]), "+f"(acc[t][3])
                : "r"(a0), "r"(a1), "r"(a2), "r"(a3), "r"(b0), "r"(b1));
        }
    }

    // epilogue: c0/c1 -> (task, col..col+1); c2/c3 -> (task+8, col..col+1)
#pragma unroll
    for (int t = 0; t < 4; t++) {
        int col = (nh * 4 + t) * 8 + 2 * tg;
        float b0v = btask[col], b1v = btask[col + 1];
        int task0 = tb + mi * 16 + g;
        int task1 = task0 + 8;
        if (task0 < N_TASK) {
            __half2 o = __floats2half2_rn(tanh_fast(acc[t][0] + b0v),
                                          tanh_fast(acc[t][1] + b1v));
            *(__half2*)&g_h_task[task0 * 64 + col] = o;
        }
        if (task1 < N_TASK) {
            __half2 o = __floats2half2_rn(tanh_fast(acc[t][2] + b0v),
                                          tanh_fast(acc[t][3] + b1v));
            *(__half2*)&g_h_task[task1 * 64 + col] = o;
        }
    }
}

// ---------------- link mean: warp per link node, CSR gather (fp16 h) ------
__global__ void k_linkmean(float* __restrict__ out) {
    int gw = (blockIdx.x * blockDim.x + threadIdx.x) >> 5;
    if (gw >= N_LINKN) return;
    int lane = threadIdx.x & 31;
    int beg = g_offs[gw];
    int n = g_cnt[gw];
    float ax = 0.f, ay = 0.f;
    int j = 0;
    for (; j + 3 < n; j += 4) {
        int t0 = __ldg(&g_csr[beg + j + 0]);
        int t1 = __ldg(&g_csr[beg + j + 1]);
        int t2 = __ldg(&g_csr[beg + j + 2]);
        int t3 = __ldg(&g_csr[beg + j + 3]);
        float2 v0 = __half22float2(*(const __half2*)&g_h_task[t0 * 64 + lane * 2]);
        float2 v1 = __half22float2(*(const __half2*)&g_h_task[t1 * 64 + lane * 2]);
        float2 v2 = __half22float2(*(const __half2*)&g_h_task[t2 * 64 + lane * 2]);
        float2 v3 = __half22float2(*(const __half2*)&g_h_task[t3 * 64 + lane * 2]);
        ax += (v0.x + v1.x) + (v2.x + v3.x);
        ay += (v0.y + v1.y) + (v2.y + v3.y);
    }
    for (; j < n; j++) {
        int t = __ldg(&g_csr[beg + j]);
        float2 v = __half22float2(*(const __half2*)&g_h_task[t * 64 + lane * 2]);
        ax += v.x;
        ay += v.y;
    }
    float inv = (n > 0) ? 1.0f / (float)n : 0.f;
    float2 o;
    o.x = ax * inv;
    o.y = ay * inv;
    *(float2*)&out[(size_t)gw * 64 + lane * 2] = o;
}

// ---------------- launch ----------------
extern "C" void kernel_launch(void* const* d_in, const int* in_sizes, int n_in,
                              void* d_out, int out_size) {
    const float* feat_ret  = (const float*)d_in[0];
    const float* feat_dram = (const float*)d_in[1];
    const float* feat_link = (const float*)d_in[2];
    const float* W_ret   = (const float*)d_in[3];
    const float* b_ret   = (const float*)d_in[4];
    const float* W_dram  = (const float*)d_in[5];
    const float* b_dram  = (const float*)d_in[6];
    const float* W_link  = (const float*)d_in[7];
    const float* b_link  = (const float*)d_in[8];
    const float* W_task  = (const float*)d_in[9];
    const float* b_task  = (const float*)d_in[10];
    const int* task_ret  = (const int*)d_in[11];
    const int* mod_ret   = (const int*)d_in[12];
    const int* task_dram = (const int*)d_in[13];
    const int* mod_dram  = (const int*)d_in[14];
    const int* task_link = (const int*)d_in[15];
    const int* mod_link  = (const int*)d_in[16];
    float* out = (float*)d_out;

    const int TPB = 256;
    // sV(25600) + sW(25600) + sMM(1536) + sWe(768) + sBe(768) = 54272 B
    const int smem_task = 64 * 100 * 4 * 2 + 192 * 8 + 192 * 4 + 192 * 4;
    cudaFuncSetAttribute(k_task, cudaFuncAttributeMaxDynamicSharedMemorySize, smem_task);

    k_init<<<(N_LINKN + TPB - 1) / TPB, TPB>>>();

    k_sum<<<(NE_ALL + 3 * N_TASK + TPB - 1) / TPB, TPB>>>(feat_link, mod_link,
                                                          feat_ret,  mod_ret,
                                                          feat_dram, mod_dram);

    k_scan<<<SCAN_NBLK, 256>>>();

    k_mm<<<(NE_ALL + TPB - 1) / TPB, TPB>>>(mod_link, task_link,
                                            mod_ret,  task_ret,
                                            mod_dram, task_dram);

    k_task<<<(N_TASK + 63) / 64, TPB, smem_task>>>(W_ret, b_ret, W_dram, b_dram,
                                                   W_link, b_link, W_task, b_task);

    k_linkmean<<<(N_LINKN * 32 + TPB - 1) / TPB, TPB>>>(out);
}